// round 13
// baseline (speedup 1.0000x reference)
#include <cuda_runtime.h>
#include <cuda_bf16.h>
#include <math_constants.h>
#include <cstdint>

#define NQ   65536
#define DIM  64
#define NK   8192
#define KSP  192            // split-K: A=[hi|lo|hi], B=[hi|hi|lo]
#define MARGIN 1e-4f

#define ZQ_OFF   0
#define LOSS_OFF 4194304
#define ENC_OFF  4194305
#define CS_OFF   4259841
#define EA_OFF   4268033
#define W_OFF    4792321

// ---------------- scratch (device globals; no allocs) ----------------------
__device__ float  g_zn[(size_t)NQ * DIM];
__device__ float  g_w2[NK];
__device__ int    g_enc[NQ];
__device__ float  g_bins[NK];
__device__ float  g_es[(size_t)NK * DIM];
__device__ double g_loss;
__device__ __align__(16) __nv_bfloat16 g_zs[(size_t)NQ * KSP];
__device__ __align__(16) __nv_bfloat16 g_ws[(size_t)NK * KSP];
__device__ int    g_nflag;
__device__ int    g_flaglist[NQ];

// ---------------- PTX helpers (baseline ISA only) ---------------------------
__device__ __forceinline__ uint32_t smem_u32(const void* p) {
    uint32_t a;
    asm("{ .reg .u64 t; cvta.to.shared.u64 t, %1; cvt.u32.u64 %0, t; }" : "=r"(a) : "l"(p));
    return a;
}
#define LDSM4(r0, r1, r2, r3, addr) \
    asm volatile("ldmatrix.sync.aligned.m8n8.x4.shared.b16 {%0,%1,%2,%3}, [%4];" \
                 : "=r"(r0), "=r"(r1), "=r"(r2), "=r"(r3) : "r"(addr))
#define MMA16816(d0, d1, d2, d3, a0, a1, a2, a3, b0, b1) \
    asm volatile("mma.sync.aligned.m16n8k16.row.col.f32.bf16.bf16.f32 " \
                 "{%0,%1,%2,%3}, {%4,%5,%6,%7}, {%8,%9}, {%0,%1,%2,%3};" \
                 : "+f"(d0), "+f"(d1), "+f"(d2), "+f"(d3) \
                 : "r"(a0), "r"(a1), "r"(a2), "r"(a3), "r"(b0), "r"(b1))
#define CP_ASYNC16(saddr, gptr) \
    asm volatile("cp.async.cg.shared.global [%0], [%1], 16;" :: "r"(saddr), "l"(gptr))
#define CP_COMMIT() asm volatile("cp.async.commit_group;" ::: "memory")
#define CP_WAIT(n)  asm volatile("cp.async.wait_group %0;" :: "n"(n) : "memory")

// smem tile geometry: 128 rows x 192 bf16, padded pitch 400 B
#define PITCH 400
#define TILE_SM (128 * PITCH)      // 51200 B

// ---------------- kernel 0: zero scratch -----------------------------------
__global__ void k_zero() {
    int idx = blockIdx.x * blockDim.x + threadIdx.x;
    if (idx < NK * DIM) g_es[idx] = 0.0f;
    int j = idx - NK * DIM;
    if (j >= 0 && j < NK) g_bins[j] = 0.0f;
    if (idx == 0) { g_loss = 0.0; g_nflag = 0; }
}

// ---------------- kernel 1: normalize z + bf16 split ------------------------
__global__ void k_prep_z(const float* __restrict__ Z) {
    int warp = (blockIdx.x * blockDim.x + threadIdx.x) >> 5;
    int lane = threadIdx.x & 31;
    if (warp >= NQ) return;
    float2 v = reinterpret_cast<const float2*>(Z)[(size_t)warp * 32 + lane];
    float ss = v.x * v.x + v.y * v.y;
    #pragma unroll
    for (int off = 16; off > 0; off >>= 1) ss += __shfl_xor_sync(0xffffffffu, ss, off);
    float inv = 1.0f / fmaxf(sqrtf(ss), 1e-12f);
    float zx = v.x * inv, zy = v.y * inv;
    reinterpret_cast<float2*>(g_zn)[(size_t)warp * 32 + lane] = make_float2(zx, zy);
    __nv_bfloat16 hx = __float2bfloat16(zx), hy = __float2bfloat16(zy);
    __nv_bfloat16 lx = __float2bfloat16(zx - __bfloat162float(hx));
    __nv_bfloat16 ly = __float2bfloat16(zy - __bfloat162float(hy));
    __nv_bfloat162 h2; h2.x = hx; h2.y = hy;
    __nv_bfloat162 l2; l2.x = lx; l2.y = ly;
    __nv_bfloat16* row = g_zs + (size_t)warp * KSP;
    reinterpret_cast<__nv_bfloat162*>(row)[lane]       = h2;
    reinterpret_cast<__nv_bfloat162*>(row + 64)[lane]  = l2;
    reinterpret_cast<__nv_bfloat162*>(row + 128)[lane] = h2;
}

// ---------------- kernel 2: w2 + bf16 split of W ----------------------------
__global__ void k_prep_w(const float* __restrict__ W) {
    int warp = (blockIdx.x * blockDim.x + threadIdx.x) >> 5;
    int lane = threadIdx.x & 31;
    if (warp >= NK) return;
    float2 v = reinterpret_cast<const float2*>(W)[(size_t)warp * 32 + lane];
    float ss = v.x * v.x + v.y * v.y;
    #pragma unroll
    for (int off = 16; off > 0; off >>= 1) ss += __shfl_xor_sync(0xffffffffu, ss, off);
    if (lane == 0) g_w2[warp] = ss;
    __nv_bfloat16 hx = __float2bfloat16(v.x), hy = __float2bfloat16(v.y);
    __nv_bfloat16 lx = __float2bfloat16(v.x - __bfloat162float(hx));
    __nv_bfloat16 ly = __float2bfloat16(v.y - __bfloat162float(hy));
    __nv_bfloat162 h2; h2.x = hx; h2.y = hy;
    __nv_bfloat162 l2; l2.x = lx; l2.y = ly;
    __nv_bfloat16* row = g_ws + (size_t)warp * KSP;
    reinterpret_cast<__nv_bfloat162*>(row)[lane]       = h2;
    reinterpret_cast<__nv_bfloat162*>(row + 64)[lane]  = h2;
    reinterpret_cast<__nv_bfloat162*>(row + 128)[lane] = l2;
}

// ---------------- kernel 3: HMMA argmax-dot filter --------------------------
// 1024 blocks x 256 threads, 2 blocks/SM. Block: 64 queries. A fragments
// register-resident; B tiles stream through a 2-buffer cp.async ring.
__device__ __forceinline__ void load_b_tile(uint32_t sdst, int kt, int tid) {
    const char* src = (const char*)g_ws + (size_t)kt * 128 * (KSP * 2);
    #pragma unroll
    for (int i = 0; i < 12; ++i) {
        int idx = i * 256 + tid;                 // 3072 16B chunks
        int row = idx / 24, c = idx % 24;
        CP_ASYNC16(sdst + row * PITCH + c * 16, src + row * (KSP * 2) + c * 16);
    }
}

__global__ __launch_bounds__(256, 2) void k_mma() {
    extern __shared__ char smraw[];
    const uint32_t s0 = smem_u32(smraw);
    const uint32_t buf0 = s0, buf1 = s0 + TILE_SM;
    float* mBst = reinterpret_cast<float*>(smraw + 2 * TILE_SM);
    int*   mIdx = reinterpret_cast<int*>(smraw + 2 * TILE_SM + 1024);
    float* mSec = reinterpret_cast<float*>(smraw + 2 * TILE_SM + 2048);

    const int tid = threadIdx.x, wid = tid >> 5, lane = tid & 31;
    const int rtile = wid & 3, h = wid >> 2;
    const int q0 = blockIdx.x * 64;

    // stage A (64 queries) through buf0, extract fragments to registers
    {
        const char* srcA = (const char*)g_zs + (size_t)q0 * (KSP * 2);
        #pragma unroll
        for (int i = 0; i < 6; ++i) {
            int idx = i * 256 + tid;             // 1536 16B chunks
            int row = idx / 24, c = idx % 24;
            CP_ASYNC16(buf0 + row * PITCH + c * 16, srcA + row * (KSP * 2) + c * 16);
        }
        CP_COMMIT();
        CP_WAIT(0);
        __syncthreads();
    }
    uint32_t af[12][4];
    {
        const uint32_t aaddr = buf0 + (rtile * 16 + (lane & 15)) * PITCH + ((lane >> 4) << 4);
        #pragma unroll
        for (int s = 0; s < 12; ++s)
            LDSM4(af[s][0], af[s][1], af[s][2], af[s][3], aaddr + s * 32);
    }
    __syncthreads();                             // everyone done reading A from buf0

    load_b_tile(buf0, 0, tid);
    CP_COMMIT();

    const uint32_t boff = (uint32_t)((h * 64 + ((lane >> 4) << 3) + (lane & 7)) * PITCH
                                     + (((lane >> 3) & 1) << 4));

    float v0b = -CUDART_INF_F, v0s = -CUDART_INF_F;
    float v1b = -CUDART_INF_F, v1s = -CUDART_INF_F;
    int   i0 = 0, i1 = 0;

    for (int kt = 0; kt < 64; ++kt) {
        if (kt + 1 < 64) {                       // prefetch kt+1 into other buffer
            load_b_tile((kt + 1) & 1 ? buf1 : buf0, kt + 1, tid);
            CP_COMMIT();
            CP_WAIT(1);                          // tile kt resident, kt+1 in flight
        } else {
            CP_WAIT(0);                          // last tile: fully resident
        }
        __syncthreads();
        const uint32_t cur = (kt & 1) ? buf1 : buf0;

        float acc[32];
        #pragma unroll
        for (int i = 0; i < 32; ++i) acc[i] = 0.0f;

        #pragma unroll
        for (int s = 0; s < 12; ++s) {
            #pragma unroll
            for (int p = 0; p < 4; ++p) {
                uint32_t b0, b1, b2, b3;
                LDSM4(b0, b1, b2, b3, cur + boff + p * 16 * PITCH + s * 32);
                float* d0 = acc + (2 * p) * 4;
                float* d1 = acc + (2 * p + 1) * 4;
                MMA16816(d0[0], d0[1], d0[2], d0[3], af[s][0], af[s][1], af[s][2], af[s][3], b0, b1);
                MMA16816(d1[0], d1[1], d1[2], d1[3], af[s][0], af[s][1], af[s][2], af[s][3], b2, b3);
            }
        }

        // per-thread top-2 update (ascending col index preserves tie rule)
        int colb = kt * 128 + h * 64 + 2 * (lane & 3);
        #pragma unroll
        for (int t = 0; t < 8; ++t) {
            int cb = colb + t * 8;
            float e0 = acc[t * 4 + 0], e1 = acc[t * 4 + 1];
            float e2 = acc[t * 4 + 2], e3 = acc[t * 4 + 3];
            if (e0 > v0b) { v0s = v0b; v0b = e0; i0 = cb; }     else if (e0 > v0s) v0s = e0;
            if (e1 > v0b) { v0s = v0b; v0b = e1; i0 = cb + 1; } else if (e1 > v0s) v0s = e1;
            if (e2 > v1b) { v1s = v1b; v1b = e2; i1 = cb; }     else if (e2 > v1s) v1s = e2;
            if (e3 > v1b) { v1s = v1b; v1b = e3; i1 = cb + 1; } else if (e3 > v1s) v1s = e3;
        }
        __syncthreads();                         // done reading cur before overwrite
    }

    // quad reduce (lanes sharing a row)
    #pragma unroll
    for (int off = 1; off <= 2; off <<= 1) {
        float ov = __shfl_xor_sync(0xffffffffu, v0b, off);
        int   oi = __shfl_xor_sync(0xffffffffu, i0, off);
        float os = __shfl_xor_sync(0xffffffffu, v0s, off);
        if (ov > v0b || (ov == v0b && oi < i0)) { v0s = fmaxf(v0b, os); v0b = ov; i0 = oi; }
        else v0s = fmaxf(v0s, ov);
        ov = __shfl_xor_sync(0xffffffffu, v1b, off);
        oi = __shfl_xor_sync(0xffffffffu, i1, off);
        os = __shfl_xor_sync(0xffffffffu, v1s, off);
        if (ov > v1b || (ov == v1b && oi < i1)) { v1s = fmaxf(v1b, os); v1b = ov; i1 = oi; }
        else v1s = fmaxf(v1s, ov);
    }
    if ((lane & 3) == 0) {
        int row0 = rtile * 16 + (lane >> 2);
        mBst[h * 64 + row0] = v0b; mIdx[h * 64 + row0] = i0; mSec[h * 64 + row0] = v0s;
        mBst[h * 64 + row0 + 8] = v1b; mIdx[h * 64 + row0 + 8] = i1; mSec[h * 64 + row0 + 8] = v1s;
    }
    __syncthreads();

    if (tid < 64) {
        float vA = mBst[tid], vB = mBst[64 + tid];
        int   iA = mIdx[tid], iB = mIdx[64 + tid];
        float sA2 = mSec[tid], sB2 = mSec[64 + tid];
        float bv; int bidx; float sv;
        if (vB > vA || (vB == vA && iB < iA)) { bv = vB; bidx = iB; sv = vA; }
        else                                  { bv = vA; bidx = iA; sv = vB; }
        sv = fmaxf(sv, fmaxf(sA2, sB2));
        g_enc[q0 + tid] = bidx;
        if (bv - sv < MARGIN) {
            int s = atomicAdd(&g_nflag, 1);
            g_flaglist[s] = q0 + tid;
        }
    }
}

// ---------------- kernel 4: exact fp32 rescore of flagged queries -----------
__global__ void k_rescore(const float* __restrict__ W) {
    __shared__ float zrow[64];
    __shared__ float rb[256];
    __shared__ int   ri[256];
    int nf = g_nflag;
    for (int it = blockIdx.x; it < nf; it += gridDim.x) {
        int q = g_flaglist[it];
        if (threadIdx.x < 16)
            reinterpret_cast<float4*>(zrow)[threadIdx.x] =
                reinterpret_cast<const float4*>(g_zn + (size_t)q * 64)[threadIdx.x];
        __syncthreads();
        float best = CUDART_INF_F; int bi = 0;
        for (int k = threadIdx.x; k < NK; k += 256) {
            const float4* wr = reinterpret_cast<const float4*>(W + (size_t)k * 64);
            float dot = 0.0f;
            #pragma unroll
            for (int c = 0; c < 16; ++c) {
                float4 wv = wr[c];
                dot += zrow[c * 4] * wv.x + zrow[c * 4 + 1] * wv.y
                     + zrow[c * 4 + 2] * wv.z + zrow[c * 4 + 3] * wv.w;
            }
            float s = fmaf(-2.0f, dot, g_w2[k]);
            if (s < best) { best = s; bi = k; }
        }
        rb[threadIdx.x] = best; ri[threadIdx.x] = bi;
        __syncthreads();
        for (int off = 128; off > 0; off >>= 1) {
            if (threadIdx.x < off) {
                float ov = rb[threadIdx.x + off]; int oi = ri[threadIdx.x + off];
                if (ov < rb[threadIdx.x] ||
                    (ov == rb[threadIdx.x] && oi < ri[threadIdx.x])) {
                    rb[threadIdx.x] = ov; ri[threadIdx.x] = oi;
                }
            }
            __syncthreads();
        }
        if (threadIdx.x == 0) g_enc[q] = ri[0];
        __syncthreads();
    }
}

// ---------------- kernel 5: scatter / z_q / loss ----------------------------
__global__ void k_scatter(const float* __restrict__ W, float* __restrict__ out) {
    __shared__ double lsum[8];
    int warp = (blockIdx.x * blockDim.x + threadIdx.x) >> 5;
    int lwid = (threadIdx.x >> 5);
    int lane = threadIdx.x & 31;
    double part_d = 0.0;
    if (warp < NQ) {
        int e = g_enc[warp];
        float2 wv = reinterpret_cast<const float2*>(W)[(size_t)e * 32 + lane];
        float2 zv = reinterpret_cast<const float2*>(g_zn)[(size_t)warp * 32 + lane];
        float d0 = wv.x - zv.x, d1 = wv.y - zv.y;
        reinterpret_cast<float2*>(out + ZQ_OFF)[(size_t)warp * 32 + lane] =
            make_float2(zv.x + d0, zv.y + d1);
        atomicAdd(&g_es[(size_t)e * 64 + 2 * lane],     zv.x);
        atomicAdd(&g_es[(size_t)e * 64 + 2 * lane + 1], zv.y);
        float part = d0 * d0 + d1 * d1;
        #pragma unroll
        for (int off = 16; off > 0; off >>= 1) part += __shfl_xor_sync(0xffffffffu, part, off);
        if (lane == 0) {
            atomicAdd(&g_bins[e], 1.0f);
            out[ENC_OFF + warp] = (float)e;
            part_d = (double)part;
        }
    }
    if (lane == 0) lsum[lwid] = part_d;
    __syncthreads();
    if (threadIdx.x == 0) {
        double s = 0.0;
        #pragma unroll
        for (int i = 0; i < 8; ++i) s += lsum[i];
        atomicAdd(&g_loss, s);
    }
}

// ---------------- kernel 6: per-code EMA updates ----------------------------
__global__ void k_update(const float* __restrict__ W,
                         const float* __restrict__ CS,
                         const float* __restrict__ EA,
                         float* __restrict__ out) {
    int warp = (blockIdx.x * blockDim.x + threadIdx.x) >> 5;
    int lane = threadIdx.x & 31;
    if (blockIdx.x == 0 && threadIdx.x == 0)
        out[LOSS_OFF] = (float)(0.25 * (g_loss / (double)((size_t)NQ * DIM)));
    if (warp >= NK) return;
    int k = warp;
    float b = g_bins[k];
    float2 es = reinterpret_cast<const float2*>(g_es)[(size_t)k * 32 + lane];
    float2 ea = reinterpret_cast<const float2*>(EA)[(size_t)k * 32 + lane];
    out[EA_OFF + (size_t)k * 64 + 2 * lane]     = ea.x * 0.99f + 0.01f * es.x;
    out[EA_OFF + (size_t)k * 64 + 2 * lane + 1] = ea.y * 0.99f + 0.01f * es.y;
    float bc = (b == 0.0f) ? 1.0f : b;
    float vx = es.x / bc, vy = es.y / bc;
    float ss = vx * vx + vy * vy;
    #pragma unroll
    for (int off = 16; off > 0; off >>= 1) ss += __shfl_xor_sync(0xffffffffu, ss, off);
    float inv = 1.0f / fmaxf(sqrtf(ss), 1e-12f);
    float2 wv = reinterpret_cast<const float2*>(W)[(size_t)k * 32 + lane];
    float enx = (b == 0.0f) ? wv.x : vx * inv;
    float eny = (b == 0.0f) ? wv.y : vy * inv;
    float nwx = wv.x * 0.99f + 0.01f * enx;
    float nwy = wv.y * 0.99f + 0.01f * eny;
    float ss2 = nwx * nwx + nwy * nwy;
    #pragma unroll
    for (int off = 16; off > 0; off >>= 1) ss2 += __shfl_xor_sync(0xffffffffu, ss2, off);
    float inv2 = 1.0f / fmaxf(sqrtf(ss2), 1e-12f);
    out[W_OFF + (size_t)k * 64 + 2 * lane]     = nwx * inv2;
    out[W_OFF + (size_t)k * 64 + 2 * lane + 1] = nwy * inv2;
    if (lane == 0) out[CS_OFF + k] = CS[k] * 0.99f + 0.01f * b;
}

// ---------------- launch -----------------------------------------------------
extern "C" void kernel_launch(void* const* d_in, const int* in_sizes, int n_in,
                              void* d_out, int out_size) {
    const float* z  = (const float*)d_in[0];
    const float* w  = (const float*)d_in[1];
    const float* cs = (const float*)d_in[2];
    const float* ea = (const float*)d_in[3];
    float* out = (float*)d_out;

    const int smem_mma = 2 * TILE_SM + 3072;   // 105,472 B -> 2 blocks/SM
    cudaFuncSetAttribute(k_mma, cudaFuncAttributeMaxDynamicSharedMemorySize, smem_mma);

    k_zero<<<(NK * DIM + NK + 255) / 256, 256>>>();
    k_prep_z<<<NQ / 8, 256>>>(z);
    k_prep_w<<<NK / 8, 256>>>(w);
    k_mma<<<NQ / 64, 256, smem_mma>>>();
    k_rescore<<<512, 256>>>(w);
    k_scatter<<<NQ / 8, 256>>>(w, out);
    k_update<<<NK / 8, 256>>>(w, cs, ea, out);
}

// round 14
// speedup vs baseline: 1.3438x; 1.3438x over previous
#include <cuda_runtime.h>
#include <cuda_bf16.h>
#include <math_constants.h>
#include <cstdint>

#define NQ   65536
#define DIM  64
#define NK   8192
#define KSP  192            // split-K: A=[hi|lo|hi], B=[hi|hi|lo]
#define MARGIN 1e-4f

#define ZQ_OFF   0
#define LOSS_OFF 4194304
#define ENC_OFF  4194305
#define CS_OFF   4259841
#define EA_OFF   4268033
#define W_OFF    4792321

// ---------------- scratch (device globals; no allocs) ----------------------
__device__ float  g_zn[(size_t)NQ * DIM];
__device__ float  g_w2[NK];
__device__ int    g_enc[NQ];
__device__ float  g_bins[NK];
__device__ float  g_es[(size_t)NK * DIM];
__device__ double g_loss;
__device__ __align__(16) __nv_bfloat16 g_zs[(size_t)NQ * KSP];
__device__ __align__(16) __nv_bfloat16 g_ws[(size_t)NK * KSP];
__device__ int    g_nflag;
__device__ int    g_flaglist[NQ];

// ---------------- PTX helpers (baseline ISA only) ---------------------------
__device__ __forceinline__ uint32_t smem_u32(const void* p) {
    uint32_t a;
    asm("{ .reg .u64 t; cvta.to.shared.u64 t, %1; cvt.u32.u64 %0, t; }" : "=r"(a) : "l"(p));
    return a;
}
#define LDSM4(r0, r1, r2, r3, addr) \
    asm volatile("ldmatrix.sync.aligned.m8n8.x4.shared.b16 {%0,%1,%2,%3}, [%4];" \
                 : "=r"(r0), "=r"(r1), "=r"(r2), "=r"(r3) : "r"(addr))
#define MMA16816(d0, d1, d2, d3, a0, a1, a2, a3, b0, b1) \
    asm volatile("mma.sync.aligned.m16n8k16.row.col.f32.bf16.bf16.f32 " \
                 "{%0,%1,%2,%3}, {%4,%5,%6,%7}, {%8,%9}, {%0,%1,%2,%3};" \
                 : "+f"(d0), "+f"(d1), "+f"(d2), "+f"(d3) \
                 : "r"(a0), "r"(a1), "r"(a2), "r"(a3), "r"(b0), "r"(b1))
#define CP_ASYNC16(saddr, gptr) \
    asm volatile("cp.async.cg.shared.global [%0], [%1], 16;" :: "r"(saddr), "l"(gptr))
#define CP_COMMIT() asm volatile("cp.async.commit_group;" ::: "memory")
#define CP_WAIT(n)  asm volatile("cp.async.wait_group %0;" :: "n"(n) : "memory")

// smem tile geometry: 128 rows x 192 bf16, padded pitch 400 B
#define PITCH 400
#define TILE_SM (128 * PITCH)      // 51200 B

// ---------------- kernel 0: zero scratch -----------------------------------
__global__ void k_zero() {
    int idx = blockIdx.x * blockDim.x + threadIdx.x;
    if (idx < NK * DIM) g_es[idx] = 0.0f;
    int j = idx - NK * DIM;
    if (j >= 0 && j < NK) g_bins[j] = 0.0f;
    if (idx == 0) { g_loss = 0.0; g_nflag = 0; }
}

// ---------------- kernel 1: normalize z + bf16 split ------------------------
__global__ void k_prep_z(const float* __restrict__ Z) {
    int warp = (blockIdx.x * blockDim.x + threadIdx.x) >> 5;
    int lane = threadIdx.x & 31;
    if (warp >= NQ) return;
    float2 v = reinterpret_cast<const float2*>(Z)[(size_t)warp * 32 + lane];
    float ss = v.x * v.x + v.y * v.y;
    #pragma unroll
    for (int off = 16; off > 0; off >>= 1) ss += __shfl_xor_sync(0xffffffffu, ss, off);
    float inv = 1.0f / fmaxf(sqrtf(ss), 1e-12f);
    float zx = v.x * inv, zy = v.y * inv;
    reinterpret_cast<float2*>(g_zn)[(size_t)warp * 32 + lane] = make_float2(zx, zy);
    __nv_bfloat16 hx = __float2bfloat16(zx), hy = __float2bfloat16(zy);
    __nv_bfloat16 lx = __float2bfloat16(zx - __bfloat162float(hx));
    __nv_bfloat16 ly = __float2bfloat16(zy - __bfloat162float(hy));
    __nv_bfloat162 h2; h2.x = hx; h2.y = hy;
    __nv_bfloat162 l2; l2.x = lx; l2.y = ly;
    __nv_bfloat16* row = g_zs + (size_t)warp * KSP;
    reinterpret_cast<__nv_bfloat162*>(row)[lane]       = h2;
    reinterpret_cast<__nv_bfloat162*>(row + 64)[lane]  = l2;
    reinterpret_cast<__nv_bfloat162*>(row + 128)[lane] = h2;
}

// ---------------- kernel 2: w2 + bf16 split of W ----------------------------
__global__ void k_prep_w(const float* __restrict__ W) {
    int warp = (blockIdx.x * blockDim.x + threadIdx.x) >> 5;
    int lane = threadIdx.x & 31;
    if (warp >= NK) return;
    float2 v = reinterpret_cast<const float2*>(W)[(size_t)warp * 32 + lane];
    float ss = v.x * v.x + v.y * v.y;
    #pragma unroll
    for (int off = 16; off > 0; off >>= 1) ss += __shfl_xor_sync(0xffffffffu, ss, off);
    if (lane == 0) g_w2[warp] = ss;
    __nv_bfloat16 hx = __float2bfloat16(v.x), hy = __float2bfloat16(v.y);
    __nv_bfloat16 lx = __float2bfloat16(v.x - __bfloat162float(hx));
    __nv_bfloat16 ly = __float2bfloat16(v.y - __bfloat162float(hy));
    __nv_bfloat162 h2; h2.x = hx; h2.y = hy;
    __nv_bfloat162 l2; l2.x = lx; l2.y = ly;
    __nv_bfloat16* row = g_ws + (size_t)warp * KSP;
    reinterpret_cast<__nv_bfloat162*>(row)[lane]       = h2;
    reinterpret_cast<__nv_bfloat162*>(row + 64)[lane]  = h2;
    reinterpret_cast<__nv_bfloat162*>(row + 128)[lane] = l2;
}

// ---------------- kernel 3: HMMA argmax-dot filter --------------------------
// 512 blocks x 512 threads (1 block/SM). A fragments register-resident;
// B tiles stream through a 4-buffer cp.async ring with prefetch distance 3.
// ONE barrier per tile: buffer (kt+3)%4 was last read at iter kt-1, so the
// top-of-loop sync is exactly the overwrite guard.
__device__ __forceinline__ void load_b_tile(uint32_t sdst, int kt, int tid) {
    const char* src = (const char*)g_ws + (size_t)kt * 128 * (KSP * 2);
    #pragma unroll
    for (int i = 0; i < 6; ++i) {
        int idx = i * 512 + tid;                 // 3072 16B chunks
        int row = idx / 24, c = idx % 24;
        CP_ASYNC16(sdst + row * PITCH + c * 16, src + row * (KSP * 2) + c * 16);
    }
}

__global__ __launch_bounds__(512, 1) void k_mma() {
    extern __shared__ char smraw[];
    const uint32_t s0 = smem_u32(smraw);
    uint32_t bufs[4] = { s0, s0 + TILE_SM, s0 + 2 * TILE_SM, s0 + 3 * TILE_SM };
    float* mBst = reinterpret_cast<float*>(smraw + 4 * TILE_SM);
    int*   mIdx = reinterpret_cast<int*>(smraw + 4 * TILE_SM + 1024);
    float* mSec = reinterpret_cast<float*>(smraw + 4 * TILE_SM + 2048);

    const int tid = threadIdx.x, wid = tid >> 5, lane = tid & 31;
    const int rtile = wid & 7, h = wid >> 3;
    const int q0 = blockIdx.x * 128;

    // prologue: A into buf3; B tiles 0..2 into buf0..2
    {
        const char* srcA = (const char*)g_zs + (size_t)q0 * (KSP * 2);
        #pragma unroll
        for (int i = 0; i < 6; ++i) {
            int idx = i * 512 + tid;
            int row = idx / 24, c = idx % 24;
            CP_ASYNC16(bufs[3] + row * PITCH + c * 16, srcA + row * (KSP * 2) + c * 16);
        }
        CP_COMMIT();
        load_b_tile(bufs[0], 0, tid); CP_COMMIT();
        load_b_tile(bufs[1], 1, tid); CP_COMMIT();
        load_b_tile(bufs[2], 2, tid); CP_COMMIT();
    }
    CP_WAIT(3);          // A resident (tiles 0..2 may be in flight)
    __syncthreads();

    // extract all A fragments into registers (48 regs)
    uint32_t af[12][4];
    {
        const uint32_t aaddr = bufs[3] + (rtile * 16 + (lane & 15)) * PITCH + ((lane >> 4) << 4);
        #pragma unroll
        for (int s = 0; s < 12; ++s)
            LDSM4(af[s][0], af[s][1], af[s][2], af[s][3], aaddr + s * 32);
    }

    const uint32_t boff = (uint32_t)((h * 64 + ((lane >> 4) << 3) + (lane & 7)) * PITCH
                                     + (((lane >> 3) & 1) << 4));

    float v0b = -CUDART_INF_F, v0s = -CUDART_INF_F;
    float v1b = -CUDART_INF_F, v1s = -CUDART_INF_F;
    int   i0 = 0, i1 = 0;

    for (int kt = 0; kt < 64; ++kt) {
        __syncthreads();            // all warps done with tile kt-1 (kt==0: af done)
        if (kt + 3 < 64) {
            load_b_tile(bufs[(kt + 3) & 3], kt + 3, tid);
            CP_COMMIT();
            CP_WAIT(3);             // tile kt resident; kt+1..kt+3 may be in flight
        } else if (kt == 61) { CP_WAIT(2); }
        else if (kt == 62) { CP_WAIT(1); }
        else               { CP_WAIT(0); }
        const uint32_t cur = bufs[kt & 3];

        float acc[32];
        #pragma unroll
        for (int i = 0; i < 32; ++i) acc[i] = 0.0f;

        #pragma unroll
        for (int s = 0; s < 12; ++s) {
            #pragma unroll
            for (int p = 0; p < 4; ++p) {
                uint32_t b0, b1, b2, b3;
                LDSM4(b0, b1, b2, b3, cur + boff + p * 16 * PITCH + s * 32);
                float* d0 = acc + (2 * p) * 4;
                float* d1 = acc + (2 * p + 1) * 4;
                MMA16816(d0[0], d0[1], d0[2], d0[3], af[s][0], af[s][1], af[s][2], af[s][3], b0, b1);
                MMA16816(d1[0], d1[1], d1[2], d1[3], af[s][0], af[s][1], af[s][2], af[s][3], b2, b3);
            }
        }

        // per-thread top-2 update (ascending col index preserves tie rule)
        int colb = kt * 128 + h * 64 + 2 * (lane & 3);
        #pragma unroll
        for (int t = 0; t < 8; ++t) {
            int cb = colb + t * 8;
            float e0 = acc[t * 4 + 0], e1 = acc[t * 4 + 1];
            float e2 = acc[t * 4 + 2], e3 = acc[t * 4 + 3];
            if (e0 > v0b) { v0s = v0b; v0b = e0; i0 = cb; }     else if (e0 > v0s) v0s = e0;
            if (e1 > v0b) { v0s = v0b; v0b = e1; i0 = cb + 1; } else if (e1 > v0s) v0s = e1;
            if (e2 > v1b) { v1s = v1b; v1b = e2; i1 = cb; }     else if (e2 > v1s) v1s = e2;
            if (e3 > v1b) { v1s = v1b; v1b = e3; i1 = cb + 1; } else if (e3 > v1s) v1s = e3;
        }
    }

    // quad reduce (lanes sharing a row)
    #pragma unroll
    for (int off = 1; off <= 2; off <<= 1) {
        float ov = __shfl_xor_sync(0xffffffffu, v0b, off);
        int   oi = __shfl_xor_sync(0xffffffffu, i0, off);
        float os = __shfl_xor_sync(0xffffffffu, v0s, off);
        if (ov > v0b || (ov == v0b && oi < i0)) { v0s = fmaxf(v0b, os); v0b = ov; i0 = oi; }
        else v0s = fmaxf(v0s, ov);
        ov = __shfl_xor_sync(0xffffffffu, v1b, off);
        oi = __shfl_xor_sync(0xffffffffu, i1, off);
        os = __shfl_xor_sync(0xffffffffu, v1s, off);
        if (ov > v1b || (ov == v1b && oi < i1)) { v1s = fmaxf(v1b, os); v1b = ov; i1 = oi; }
        else v1s = fmaxf(v1s, ov);
    }
    __syncthreads();                // merge arrays live in ring smem region? no — separate; just order
    if ((lane & 3) == 0) {
        int row0 = rtile * 16 + (lane >> 2);
        mBst[h * 128 + row0] = v0b; mIdx[h * 128 + row0] = i0; mSec[h * 128 + row0] = v0s;
        mBst[h * 128 + row0 + 8] = v1b; mIdx[h * 128 + row0 + 8] = i1; mSec[h * 128 + row0 + 8] = v1s;
    }
    __syncthreads();

    if (tid < 128) {
        float vA = mBst[tid], vB = mBst[128 + tid];
        int   iA = mIdx[tid], iB = mIdx[128 + tid];
        float sA2 = mSec[tid], sB2 = mSec[128 + tid];
        float bv; int bidx; float sv;
        if (vB > vA || (vB == vA && iB < iA)) { bv = vB; bidx = iB; sv = vA; }
        else                                  { bv = vA; bidx = iA; sv = vB; }
        sv = fmaxf(sv, fmaxf(sA2, sB2));
        g_enc[q0 + tid] = bidx;
        if (bv - sv < MARGIN) {
            int s = atomicAdd(&g_nflag, 1);
            g_flaglist[s] = q0 + tid;
        }
    }
}

// ---------------- kernel 4: exact fp32 rescore of flagged queries -----------
__global__ void k_rescore(const float* __restrict__ W) {
    __shared__ float zrow[64];
    __shared__ float rb[256];
    __shared__ int   ri[256];
    int nf = g_nflag;
    for (int it = blockIdx.x; it < nf; it += gridDim.x) {
        int q = g_flaglist[it];
        if (threadIdx.x < 16)
            reinterpret_cast<float4*>(zrow)[threadIdx.x] =
                reinterpret_cast<const float4*>(g_zn + (size_t)q * 64)[threadIdx.x];
        __syncthreads();
        float best = CUDART_INF_F; int bi = 0;
        for (int k = threadIdx.x; k < NK; k += 256) {
            const float4* wr = reinterpret_cast<const float4*>(W + (size_t)k * 64);
            float dot = 0.0f;
            #pragma unroll
            for (int c = 0; c < 16; ++c) {
                float4 wv = wr[c];
                dot += zrow[c * 4] * wv.x + zrow[c * 4 + 1] * wv.y
                     + zrow[c * 4 + 2] * wv.z + zrow[c * 4 + 3] * wv.w;
            }
            float s = fmaf(-2.0f, dot, g_w2[k]);
            if (s < best) { best = s; bi = k; }
        }
        rb[threadIdx.x] = best; ri[threadIdx.x] = bi;
        __syncthreads();
        for (int off = 128; off > 0; off >>= 1) {
            if (threadIdx.x < off) {
                float ov = rb[threadIdx.x + off]; int oi = ri[threadIdx.x + off];
                if (ov < rb[threadIdx.x] ||
                    (ov == rb[threadIdx.x] && oi < ri[threadIdx.x])) {
                    rb[threadIdx.x] = ov; ri[threadIdx.x] = oi;
                }
            }
            __syncthreads();
        }
        if (threadIdx.x == 0) g_enc[q] = ri[0];
        __syncthreads();
    }
}

// ---------------- kernel 5: scatter / z_q / loss ----------------------------
__global__ void k_scatter(const float* __restrict__ W, float* __restrict__ out) {
    __shared__ double lsum[8];
    int warp = (blockIdx.x * blockDim.x + threadIdx.x) >> 5;
    int lwid = (threadIdx.x >> 5);
    int lane = threadIdx.x & 31;
    double part_d = 0.0;
    if (warp < NQ) {
        int e = g_enc[warp];
        float2 wv = reinterpret_cast<const float2*>(W)[(size_t)e * 32 + lane];
        float2 zv = reinterpret_cast<const float2*>(g_zn)[(size_t)warp * 32 + lane];
        float d0 = wv.x - zv.x, d1 = wv.y - zv.y;
        reinterpret_cast<float2*>(out + ZQ_OFF)[(size_t)warp * 32 + lane] =
            make_float2(zv.x + d0, zv.y + d1);
        atomicAdd(&g_es[(size_t)e * 64 + 2 * lane],     zv.x);
        atomicAdd(&g_es[(size_t)e * 64 + 2 * lane + 1], zv.y);
        float part = d0 * d0 + d1 * d1;
        #pragma unroll
        for (int off = 16; off > 0; off >>= 1) part += __shfl_xor_sync(0xffffffffu, part, off);
        if (lane == 0) {
            atomicAdd(&g_bins[e], 1.0f);
            out[ENC_OFF + warp] = (float)e;
            part_d = (double)part;
        }
    }
    if (lane == 0) lsum[lwid] = part_d;
    __syncthreads();
    if (threadIdx.x == 0) {
        double s = 0.0;
        #pragma unroll
        for (int i = 0; i < 8; ++i) s += lsum[i];
        atomicAdd(&g_loss, s);
    }
}

// ---------------- kernel 6: per-code EMA updates ----------------------------
__global__ void k_update(const float* __restrict__ W,
                         const float* __restrict__ CS,
                         const float* __restrict__ EA,
                         float* __restrict__ out) {
    int warp = (blockIdx.x * blockDim.x + threadIdx.x) >> 5;
    int lane = threadIdx.x & 31;
    if (blockIdx.x == 0 && threadIdx.x == 0)
        out[LOSS_OFF] = (float)(0.25 * (g_loss / (double)((size_t)NQ * DIM)));
    if (warp >= NK) return;
    int k = warp;
    float b = g_bins[k];
    float2 es = reinterpret_cast<const float2*>(g_es)[(size_t)k * 32 + lane];
    float2 ea = reinterpret_cast<const float2*>(EA)[(size_t)k * 32 + lane];
    out[EA_OFF + (size_t)k * 64 + 2 * lane]     = ea.x * 0.99f + 0.01f * es.x;
    out[EA_OFF + (size_t)k * 64 + 2 * lane + 1] = ea.y * 0.99f + 0.01f * es.y;
    float bc = (b == 0.0f) ? 1.0f : b;
    float vx = es.x / bc, vy = es.y / bc;
    float ss = vx * vx + vy * vy;
    #pragma unroll
    for (int off = 16; off > 0; off >>= 1) ss += __shfl_xor_sync(0xffffffffu, ss, off);
    float inv = 1.0f / fmaxf(sqrtf(ss), 1e-12f);
    float2 wv = reinterpret_cast<const float2*>(W)[(size_t)k * 32 + lane];
    float enx = (b == 0.0f) ? wv.x : vx * inv;
    float eny = (b == 0.0f) ? wv.y : vy * inv;
    float nwx = wv.x * 0.99f + 0.01f * enx;
    float nwy = wv.y * 0.99f + 0.01f * eny;
    float ss2 = nwx * nwx + nwy * nwy;
    #pragma unroll
    for (int off = 16; off > 0; off >>= 1) ss2 += __shfl_xor_sync(0xffffffffu, ss2, off);
    float inv2 = 1.0f / fmaxf(sqrtf(ss2), 1e-12f);
    out[W_OFF + (size_t)k * 64 + 2 * lane]     = nwx * inv2;
    out[W_OFF + (size_t)k * 64 + 2 * lane + 1] = nwy * inv2;
    if (lane == 0) out[CS_OFF + k] = CS[k] * 0.99f + 0.01f * b;
}

// ---------------- launch -----------------------------------------------------
extern "C" void kernel_launch(void* const* d_in, const int* in_sizes, int n_in,
                              void* d_out, int out_size) {
    const float* z  = (const float*)d_in[0];
    const float* w  = (const float*)d_in[1];
    const float* cs = (const float*)d_in[2];
    const float* ea = (const float*)d_in[3];
    float* out = (float*)d_out;

    const int smem_mma = 4 * TILE_SM + 3072;   // 207,872 B (1 block/SM)
    cudaFuncSetAttribute(k_mma, cudaFuncAttributeMaxDynamicSharedMemorySize, smem_mma);

    k_zero<<<(NK * DIM + NK + 255) / 256, 256>>>();
    k_prep_z<<<NQ / 8, 256>>>(z);
    k_prep_w<<<NK / 8, 256>>>(w);
    k_mma<<<NQ / 128, 512, smem_mma>>>();
    k_rescore<<<512, 256>>>(w);
    k_scatter<<<NQ / 8, 256>>>(w, out);
    k_update<<<NK / 8, 256>>>(w, cs, ea, out);
}

// round 15
// speedup vs baseline: 1.5278x; 1.1369x over previous
#include <cuda_runtime.h>
#include <cuda_bf16.h>
#include <math_constants.h>
#include <cstdint>

#define NQ   65536
#define DIM  64
#define NK   8192
#define KSP  192            // split-K: A=[hi|lo|hi], B=[hi|hi|lo]
#define MARGIN 1e-4f

#define ZQ_OFF   0
#define LOSS_OFF 4194304
#define ENC_OFF  4194305
#define CS_OFF   4259841
#define EA_OFF   4268033
#define W_OFF    4792321

// ---------------- scratch (device globals; no allocs) ----------------------
__device__ float  g_zn[(size_t)NQ * DIM];
__device__ float  g_w2[NK];
__device__ int    g_enc[NQ];
__device__ float  g_bins[NK];
__device__ float  g_es[(size_t)NK * DIM];
__device__ double g_loss;
__device__ __align__(16) __nv_bfloat16 g_zs[(size_t)NQ * KSP];
__device__ __align__(16) __nv_bfloat16 g_ws[(size_t)NK * KSP];
__device__ int    g_nflag;
__device__ int    g_flaglist[NQ];

// ---------------- PTX helpers (baseline ISA only) ---------------------------
__device__ __forceinline__ uint32_t smem_u32(const void* p) {
    uint32_t a;
    asm("{ .reg .u64 t; cvta.to.shared.u64 t, %1; cvt.u32.u64 %0, t; }" : "=r"(a) : "l"(p));
    return a;
}
#define LDSM4(r0, r1, r2, r3, addr) \
    asm volatile("ldmatrix.sync.aligned.m8n8.x4.shared.b16 {%0,%1,%2,%3}, [%4];" \
                 : "=r"(r0), "=r"(r1), "=r"(r2), "=r"(r3) : "r"(addr))
#define MMA16816(d0, d1, d2, d3, a0, a1, a2, a3, b0, b1) \
    asm volatile("mma.sync.aligned.m16n8k16.row.col.f32.bf16.bf16.f32 " \
                 "{%0,%1,%2,%3}, {%4,%5,%6,%7}, {%8,%9}, {%0,%1,%2,%3};" \
                 : "+f"(d0), "+f"(d1), "+f"(d2), "+f"(d3) \
                 : "r"(a0), "r"(a1), "r"(a2), "r"(a3), "r"(b0), "r"(b1))
#define CP_ASYNC16(saddr, gptr) \
    asm volatile("cp.async.cg.shared.global [%0], [%1], 16;" :: "r"(saddr), "l"(gptr))
#define CP_COMMIT() asm volatile("cp.async.commit_group;" ::: "memory")
#define CP_WAIT(n)  asm volatile("cp.async.wait_group %0;" :: "n"(n) : "memory")

// smem tile geometry: 128 rows x 192 bf16, padded pitch 400 B
#define PITCH 400
#define TILE_SM (128 * PITCH)      // 51200 B

// ---------------- kernel 1: zero scratch + normalize z + bf16 split ---------
__global__ void k_prep_z(const float* __restrict__ Z) {
    int gtid = blockIdx.x * blockDim.x + threadIdx.x;
    // fused scratch zeroing (grid = 2M threads covers all regions)
    if (gtid < NK * DIM) g_es[gtid] = 0.0f;
    if (gtid < NK) g_bins[gtid] = 0.0f;
    if (gtid == 0) { g_loss = 0.0; g_nflag = 0; }

    int warp = gtid >> 5;
    int lane = threadIdx.x & 31;
    if (warp >= NQ) return;
    float2 v = reinterpret_cast<const float2*>(Z)[(size_t)warp * 32 + lane];
    float ss = v.x * v.x + v.y * v.y;
    #pragma unroll
    for (int off = 16; off > 0; off >>= 1) ss += __shfl_xor_sync(0xffffffffu, ss, off);
    float inv = 1.0f / fmaxf(sqrtf(ss), 1e-12f);
    float zx = v.x * inv, zy = v.y * inv;
    reinterpret_cast<float2*>(g_zn)[(size_t)warp * 32 + lane] = make_float2(zx, zy);
    __nv_bfloat16 hx = __float2bfloat16(zx), hy = __float2bfloat16(zy);
    __nv_bfloat16 lx = __float2bfloat16(zx - __bfloat162float(hx));
    __nv_bfloat16 ly = __float2bfloat16(zy - __bfloat162float(hy));
    __nv_bfloat162 h2; h2.x = hx; h2.y = hy;
    __nv_bfloat162 l2; l2.x = lx; l2.y = ly;
    __nv_bfloat16* row = g_zs + (size_t)warp * KSP;
    reinterpret_cast<__nv_bfloat162*>(row)[lane]       = h2;
    reinterpret_cast<__nv_bfloat162*>(row + 64)[lane]  = l2;
    reinterpret_cast<__nv_bfloat162*>(row + 128)[lane] = h2;
}

// ---------------- kernel 2: w2 + bf16 split of W ----------------------------
__global__ void k_prep_w(const float* __restrict__ W) {
    int warp = (blockIdx.x * blockDim.x + threadIdx.x) >> 5;
    int lane = threadIdx.x & 31;
    if (warp >= NK) return;
    float2 v = reinterpret_cast<const float2*>(W)[(size_t)warp * 32 + lane];
    float ss = v.x * v.x + v.y * v.y;
    #pragma unroll
    for (int off = 16; off > 0; off >>= 1) ss += __shfl_xor_sync(0xffffffffu, ss, off);
    if (lane == 0) g_w2[warp] = ss;
    __nv_bfloat16 hx = __float2bfloat16(v.x), hy = __float2bfloat16(v.y);
    __nv_bfloat16 lx = __float2bfloat16(v.x - __bfloat162float(hx));
    __nv_bfloat16 ly = __float2bfloat16(v.y - __bfloat162float(hy));
    __nv_bfloat162 h2; h2.x = hx; h2.y = hy;
    __nv_bfloat162 l2; l2.x = lx; l2.y = ly;
    __nv_bfloat16* row = g_ws + (size_t)warp * KSP;
    reinterpret_cast<__nv_bfloat162*>(row)[lane]       = h2;
    reinterpret_cast<__nv_bfloat162*>(row + 64)[lane]  = h2;
    reinterpret_cast<__nv_bfloat162*>(row + 128)[lane] = l2;
}

// ---------------- kernel 3: HMMA argmax-dot filter --------------------------
// 512 blocks x 512 threads (1 block/SM), round-12 proven 3-buffer structure.
// A fragments register-resident; B tiles via 3-buffer cp.async ring, depth-1
// prefetch. Pairwise top-2 epilogue (FMNMX off the predicate chain).
__device__ __forceinline__ void load_b_tile(uint32_t sdst, int kt, int tid) {
    const char* src = (const char*)g_ws + (size_t)kt * 128 * (KSP * 2);
    #pragma unroll
    for (int i = 0; i < 6; ++i) {
        int idx = i * 512 + tid;                 // 3072 16B chunks
        int row = idx / 24, c = idx % 24;
        CP_ASYNC16(sdst + row * PITCH + c * 16, src + row * (KSP * 2) + c * 16);
    }
}

__global__ __launch_bounds__(512, 1) void k_mma() {
    extern __shared__ char smraw[];
    const uint32_t s0 = smem_u32(smraw);
    const uint32_t buf0 = s0, buf1 = s0 + TILE_SM, buf2 = s0 + 2 * TILE_SM;
    float* mBst = reinterpret_cast<float*>(smraw + 3 * TILE_SM);
    int*   mIdx = reinterpret_cast<int*>(smraw + 3 * TILE_SM + 1024);
    float* mSec = reinterpret_cast<float*>(smraw + 3 * TILE_SM + 2048);

    const int tid = threadIdx.x, wid = tid >> 5, lane = tid & 31;
    const int rtile = wid & 7, h = wid >> 3;
    const int q0 = blockIdx.x * 128;

    // prologue: A into buf2, B tiles 0/1 into buf0/buf1
    {
        const char* srcA = (const char*)g_zs + (size_t)q0 * (KSP * 2);
        #pragma unroll
        for (int i = 0; i < 6; ++i) {
            int idx = i * 512 + tid;
            int row = idx / 24, c = idx % 24;
            CP_ASYNC16(buf2 + row * PITCH + c * 16, srcA + row * (KSP * 2) + c * 16);
        }
        CP_COMMIT();
        load_b_tile(buf0, 0, tid); CP_COMMIT();
        load_b_tile(buf1, 1, tid); CP_COMMIT();
    }
    CP_WAIT(2);          // A resident
    __syncthreads();

    // extract all A fragments into registers (48 regs)
    uint32_t af[12][4];
    {
        const uint32_t aaddr = buf2 + (rtile * 16 + (lane & 15)) * PITCH + ((lane >> 4) << 4);
        #pragma unroll
        for (int s = 0; s < 12; ++s)
            LDSM4(af[s][0], af[s][1], af[s][2], af[s][3], aaddr + s * 32);
    }

    const uint32_t boff = (uint32_t)((h * 64 + ((lane >> 4) << 3) + (lane & 7)) * PITCH
                                     + (((lane >> 3) & 1) << 4));

    float v0b = -CUDART_INF_F, v0s = -CUDART_INF_F;
    float v1b = -CUDART_INF_F, v1s = -CUDART_INF_F;
    int   i0 = 0, i1 = 0;

    for (int kt = 0; kt < 64; ++kt) {
        if (kt == 63) { CP_WAIT(0); } else { CP_WAIT(1); }   // tile kt resident
        __syncthreads();
        if (kt + 2 < 64) {
            uint32_t nb = ((kt + 2) % 3 == 0) ? buf0 : ((kt + 2) % 3 == 1) ? buf1 : buf2;
            load_b_tile(nb, kt + 2, tid);
            CP_COMMIT();
        }
        const uint32_t cur = (kt % 3 == 0) ? buf0 : (kt % 3 == 1) ? buf1 : buf2;

        float acc[32];
        #pragma unroll
        for (int i = 0; i < 32; ++i) acc[i] = 0.0f;

        #pragma unroll
        for (int s = 0; s < 12; ++s) {
            #pragma unroll
            for (int p = 0; p < 4; ++p) {
                uint32_t b0, b1, b2, b3;
                LDSM4(b0, b1, b2, b3, cur + boff + p * 16 * PITCH + s * 32);
                float* d0 = acc + (2 * p) * 4;
                float* d1 = acc + (2 * p + 1) * 4;
                MMA16816(d0[0], d0[1], d0[2], d0[3], af[s][0], af[s][1], af[s][2], af[s][3], b0, b1);
                MMA16816(d1[0], d1[1], d1[2], d1[3], af[s][0], af[s][1], af[s][2], af[s][3], b2, b3);
            }
        }

        // pairwise top-2 epilogue: FMNMX pre-reduction, 8 guarded updates/row.
        // (Filter tie details irrelevant: anything within MARGIN is rescored.)
        int colb = kt * 128 + h * 64 + 2 * (lane & 3);
        #pragma unroll
        for (int t = 0; t < 8; ++t) {
            int cb = colb + t * 8;
            {   // row 0 pair
                float e0 = acc[t * 4 + 0], e1 = acc[t * 4 + 1];
                float m  = fmaxf(e0, e1);
                float o  = fminf(e0, e1);
                int   ci = (e1 > e0) ? cb + 1 : cb;
                bool up = (m > v0b);
                v0s = up ? fmaxf(v0b, o) : fmaxf(v0s, m);
                i0  = up ? ci : i0;
                v0b = fmaxf(v0b, m);
            }
            {   // row 1 pair
                float e2 = acc[t * 4 + 2], e3 = acc[t * 4 + 3];
                float m  = fmaxf(e2, e3);
                float o  = fminf(e2, e3);
                int   ci = (e3 > e2) ? cb + 1 : cb;
                bool up = (m > v1b);
                v1s = up ? fmaxf(v1b, o) : fmaxf(v1s, m);
                i1  = up ? ci : i1;
                v1b = fmaxf(v1b, m);
            }
        }
        __syncthreads();            // done reading cur before it's overwritten
    }

    // quad reduce (lanes sharing a row)
    #pragma unroll
    for (int off = 1; off <= 2; off <<= 1) {
        float ov = __shfl_xor_sync(0xffffffffu, v0b, off);
        int   oi = __shfl_xor_sync(0xffffffffu, i0, off);
        float os = __shfl_xor_sync(0xffffffffu, v0s, off);
        if (ov > v0b || (ov == v0b && oi < i0)) { v0s = fmaxf(v0b, os); v0b = ov; i0 = oi; }
        else v0s = fmaxf(v0s, ov);
        ov = __shfl_xor_sync(0xffffffffu, v1b, off);
        oi = __shfl_xor_sync(0xffffffffu, i1, off);
        os = __shfl_xor_sync(0xffffffffu, v1s, off);
        if (ov > v1b || (ov == v1b && oi < i1)) { v1s = fmaxf(v1b, os); v1b = ov; i1 = oi; }
        else v1s = fmaxf(v1s, ov);
    }
    if ((lane & 3) == 0) {
        int row0 = rtile * 16 + (lane >> 2);
        mBst[h * 128 + row0] = v0b; mIdx[h * 128 + row0] = i0; mSec[h * 128 + row0] = v0s;
        mBst[h * 128 + row0 + 8] = v1b; mIdx[h * 128 + row0 + 8] = i1; mSec[h * 128 + row0 + 8] = v1s;
    }
    __syncthreads();

    if (tid < 128) {
        float vA = mBst[tid], vB = mBst[128 + tid];
        int   iA = mIdx[tid], iB = mIdx[128 + tid];
        float sA2 = mSec[tid], sB2 = mSec[128 + tid];
        float bv; int bidx; float sv;
        if (vB > vA || (vB == vA && iB < iA)) { bv = vB; bidx = iB; sv = vA; }
        else                                  { bv = vA; bidx = iA; sv = vB; }
        sv = fmaxf(sv, fmaxf(sA2, sB2));
        g_enc[q0 + tid] = bidx;
        if (bv - sv < MARGIN) {
            int s = atomicAdd(&g_nflag, 1);
            g_flaglist[s] = q0 + tid;
        }
    }
}

// ---------------- kernel 4: exact fp32 rescore of flagged queries -----------
__global__ void k_rescore(const float* __restrict__ W) {
    __shared__ float zrow[64];
    __shared__ float rb[256];
    __shared__ int   ri[256];
    int nf = g_nflag;
    for (int it = blockIdx.x; it < nf; it += gridDim.x) {
        int q = g_flaglist[it];
        if (threadIdx.x < 16)
            reinterpret_cast<float4*>(zrow)[threadIdx.x] =
                reinterpret_cast<const float4*>(g_zn + (size_t)q * 64)[threadIdx.x];
        __syncthreads();
        float best = CUDART_INF_F; int bi = 0;
        for (int k = threadIdx.x; k < NK; k += 256) {
            const float4* wr = reinterpret_cast<const float4*>(W + (size_t)k * 64);
            float dot = 0.0f;
            #pragma unroll
            for (int c = 0; c < 16; ++c) {
                float4 wv = wr[c];
                dot += zrow[c * 4] * wv.x + zrow[c * 4 + 1] * wv.y
                     + zrow[c * 4 + 2] * wv.z + zrow[c * 4 + 3] * wv.w;
            }
            float s = fmaf(-2.0f, dot, g_w2[k]);
            if (s < best) { best = s; bi = k; }
        }
        rb[threadIdx.x] = best; ri[threadIdx.x] = bi;
        __syncthreads();
        for (int off = 128; off > 0; off >>= 1) {
            if (threadIdx.x < off) {
                float ov = rb[threadIdx.x + off]; int oi = ri[threadIdx.x + off];
                if (ov < rb[threadIdx.x] ||
                    (ov == rb[threadIdx.x] && oi < ri[threadIdx.x])) {
                    rb[threadIdx.x] = ov; ri[threadIdx.x] = oi;
                }
            }
            __syncthreads();
        }
        if (threadIdx.x == 0) g_enc[q] = ri[0];
        __syncthreads();
    }
}

// ---------------- kernel 5: scatter / z_q / loss ----------------------------
__global__ void k_scatter(const float* __restrict__ W, float* __restrict__ out) {
    __shared__ double lsum[8];
    int warp = (blockIdx.x * blockDim.x + threadIdx.x) >> 5;
    int lwid = (threadIdx.x >> 5);
    int lane = threadIdx.x & 31;
    double part_d = 0.0;
    if (warp < NQ) {
        int e = g_enc[warp];
        float2 wv = reinterpret_cast<const float2*>(W)[(size_t)e * 32 + lane];
        float2 zv = reinterpret_cast<const float2*>(g_zn)[(size_t)warp * 32 + lane];
        float d0 = wv.x - zv.x, d1 = wv.y - zv.y;
        reinterpret_cast<float2*>(out + ZQ_OFF)[(size_t)warp * 32 + lane] =
            make_float2(zv.x + d0, zv.y + d1);
        atomicAdd(&g_es[(size_t)e * 64 + 2 * lane],     zv.x);
        atomicAdd(&g_es[(size_t)e * 64 + 2 * lane + 1], zv.y);
        float part = d0 * d0 + d1 * d1;
        #pragma unroll
        for (int off = 16; off > 0; off >>= 1) part += __shfl_xor_sync(0xffffffffu, part, off);
        if (lane == 0) {
            atomicAdd(&g_bins[e], 1.0f);
            out[ENC_OFF + warp] = (float)e;
            part_d = (double)part;
        }
    }
    if (lane == 0) lsum[lwid] = part_d;
    __syncthreads();
    if (threadIdx.x == 0) {
        double s = 0.0;
        #pragma unroll
        for (int i = 0; i < 8; ++i) s += lsum[i];
        atomicAdd(&g_loss, s);
    }
}

// ---------------- kernel 6: per-code EMA updates ----------------------------
__global__ void k_update(const float* __restrict__ W,
                         const float* __restrict__ CS,
                         const float* __restrict__ EA,
                         float* __restrict__ out) {
    int warp = (blockIdx.x * blockDim.x + threadIdx.x) >> 5;
    int lane = threadIdx.x & 31;
    if (blockIdx.x == 0 && threadIdx.x == 0)
        out[LOSS_OFF] = (float)(0.25 * (g_loss / (double)((size_t)NQ * DIM)));
    if (warp >= NK) return;
    int k = warp;
    float b = g_bins[k];
    float2 es = reinterpret_cast<const float2*>(g_es)[(size_t)k * 32 + lane];
    float2 ea = reinterpret_cast<const float2*>(EA)[(size_t)k * 32 + lane];
    out[EA_OFF + (size_t)k * 64 + 2 * lane]     = ea.x * 0.99f + 0.01f * es.x;
    out[EA_OFF + (size_t)k * 64 + 2 * lane + 1] = ea.y * 0.99f + 0.01f * es.y;
    float bc = (b == 0.0f) ? 1.0f : b;
    float vx = es.x / bc, vy = es.y / bc;
    float ss = vx * vx + vy * vy;
    #pragma unroll
    for (int off = 16; off > 0; off >>= 1) ss += __shfl_xor_sync(0xffffffffu, ss, off);
    float inv = 1.0f / fmaxf(sqrtf(ss), 1e-12f);
    float2 wv = reinterpret_cast<const float2*>(W)[(size_t)k * 32 + lane];
    float enx = (b == 0.0f) ? wv.x : vx * inv;
    float eny = (b == 0.0f) ? wv.y : vy * inv;
    float nwx = wv.x * 0.99f + 0.01f * enx;
    float nwy = wv.y * 0.99f + 0.01f * eny;
    float ss2 = nwx * nwx + nwy * nwy;
    #pragma unroll
    for (int off = 16; off > 0; off >>= 1) ss2 += __shfl_xor_sync(0xffffffffu, ss2, off);
    float inv2 = 1.0f / fmaxf(sqrtf(ss2), 1e-12f);
    out[W_OFF + (size_t)k * 64 + 2 * lane]     = nwx * inv2;
    out[W_OFF + (size_t)k * 64 + 2 * lane + 1] = nwy * inv2;
    if (lane == 0) out[CS_OFF + k] = CS[k] * 0.99f + 0.01f * b;
}

// ---------------- launch -----------------------------------------------------
extern "C" void kernel_launch(void* const* d_in, const int* in_sizes, int n_in,
                              void* d_out, int out_size) {
    const float* z  = (const float*)d_in[0];
    const float* w  = (const float*)d_in[1];
    const float* cs = (const float*)d_in[2];
    const float* ea = (const float*)d_in[3];
    float* out = (float*)d_out;

    const int smem_mma = 3 * TILE_SM + 3072;   // 156,672 B (1 block/SM)
    cudaFuncSetAttribute(k_mma, cudaFuncAttributeMaxDynamicSharedMemorySize, smem_mma);

    k_prep_z<<<NQ / 8, 256>>>(z);
    k_prep_w<<<NK / 8, 256>>>(w);
    k_mma<<<NQ / 128, 512, smem_mma>>>();
    k_rescore<<<512, 256>>>(w);
    k_scatter<<<NQ / 8, 256>>>(w, out);
    k_update<<<NK / 8, 256>>>(w, cs, ea, out);
}

// round 16
// speedup vs baseline: 1.6556x; 1.0837x over previous
#include <cuda_runtime.h>
#include <cuda_bf16.h>
#include <math_constants.h>
#include <cstdint>

#define NQ   65536
#define DIM  64
#define NK   8192
#define KSP  192            // split-K: A=[hi|lo|hi], B=[hi|hi|lo]
#define MARGIN 1e-4f

#define ZQ_OFF   0
#define LOSS_OFF 4194304
#define ENC_OFF  4194305
#define CS_OFF   4259841
#define EA_OFF   4268033
#define W_OFF    4792321

// ---------------- scratch (device globals; no allocs) ----------------------
__device__ float  g_zn[(size_t)NQ * DIM];
__device__ float  g_w2[NK];
__device__ int    g_enc[NQ];
__device__ float  g_bins[NK];
__device__ float  g_es[(size_t)NK * DIM];
__device__ double g_loss;
__device__ __align__(16) __nv_bfloat16 g_zs[(size_t)NQ * KSP];
__device__ __align__(16) __nv_bfloat16 g_ws[(size_t)NK * KSP];
__device__ int    g_nflag;
__device__ int    g_flaglist[NQ];
__device__ unsigned long long g_rkey[NQ];

// ---------------- PTX helpers (baseline ISA only) ---------------------------
__device__ __forceinline__ uint32_t smem_u32(const void* p) {
    uint32_t a;
    asm("{ .reg .u64 t; cvta.to.shared.u64 t, %1; cvt.u32.u64 %0, t; }" : "=r"(a) : "l"(p));
    return a;
}
#define LDSM4(r0, r1, r2, r3, addr) \
    asm volatile("ldmatrix.sync.aligned.m8n8.x4.shared.b16 {%0,%1,%2,%3}, [%4];" \
                 : "=r"(r0), "=r"(r1), "=r"(r2), "=r"(r3) : "r"(addr))
#define MMA16816(d0, d1, d2, d3, a0, a1, a2, a3, b0, b1) \
    asm volatile("mma.sync.aligned.m16n8k16.row.col.f32.bf16.bf16.f32 " \
                 "{%0,%1,%2,%3}, {%4,%5,%6,%7}, {%8,%9}, {%0,%1,%2,%3};" \
                 : "+f"(d0), "+f"(d1), "+f"(d2), "+f"(d3) \
                 : "r"(a0), "r"(a1), "r"(a2), "r"(a3), "r"(b0), "r"(b1))
#define CP_ASYNC16(saddr, gptr) \
    asm volatile("cp.async.cg.shared.global [%0], [%1], 16;" :: "r"(saddr), "l"(gptr))
#define CP_COMMIT() asm volatile("cp.async.commit_group;" ::: "memory")
#define CP_WAIT(n)  asm volatile("cp.async.wait_group %0;" :: "n"(n) : "memory")

// smem tile geometry: 128 rows x 192 bf16, padded pitch 400 B
#define PITCH 400
#define TILE_SM (128 * PITCH)      // 51200 B

// ---------------- kernel 1: zero scratch + normalize z + bf16 split ---------
__global__ void k_prep_z(const float* __restrict__ Z) {
    int gtid = blockIdx.x * blockDim.x + threadIdx.x;
    if (gtid < NK * DIM) g_es[gtid] = 0.0f;
    if (gtid < NK) g_bins[gtid] = 0.0f;
    if (gtid == 0) { g_loss = 0.0; g_nflag = 0; }

    int warp = gtid >> 5;
    int lane = threadIdx.x & 31;
    if (warp >= NQ) return;
    float2 v = reinterpret_cast<const float2*>(Z)[(size_t)warp * 32 + lane];
    float ss = v.x * v.x + v.y * v.y;
    #pragma unroll
    for (int off = 16; off > 0; off >>= 1) ss += __shfl_xor_sync(0xffffffffu, ss, off);
    float inv = 1.0f / fmaxf(sqrtf(ss), 1e-12f);
    float zx = v.x * inv, zy = v.y * inv;
    reinterpret_cast<float2*>(g_zn)[(size_t)warp * 32 + lane] = make_float2(zx, zy);
    __nv_bfloat16 hx = __float2bfloat16(zx), hy = __float2bfloat16(zy);
    __nv_bfloat16 lx = __float2bfloat16(zx - __bfloat162float(hx));
    __nv_bfloat16 ly = __float2bfloat16(zy - __bfloat162float(hy));
    __nv_bfloat162 h2; h2.x = hx; h2.y = hy;
    __nv_bfloat162 l2; l2.x = lx; l2.y = ly;
    __nv_bfloat16* row = g_zs + (size_t)warp * KSP;
    reinterpret_cast<__nv_bfloat162*>(row)[lane]       = h2;
    reinterpret_cast<__nv_bfloat162*>(row + 64)[lane]  = l2;
    reinterpret_cast<__nv_bfloat162*>(row + 128)[lane] = h2;
}

// ---------------- kernel 2: w2 + bf16 split of W ----------------------------
__global__ void k_prep_w(const float* __restrict__ W) {
    int warp = (blockIdx.x * blockDim.x + threadIdx.x) >> 5;
    int lane = threadIdx.x & 31;
    if (warp >= NK) return;
    float2 v = reinterpret_cast<const float2*>(W)[(size_t)warp * 32 + lane];
    float ss = v.x * v.x + v.y * v.y;
    #pragma unroll
    for (int off = 16; off > 0; off >>= 1) ss += __shfl_xor_sync(0xffffffffu, ss, off);
    if (lane == 0) g_w2[warp] = ss;
    __nv_bfloat16 hx = __float2bfloat16(v.x), hy = __float2bfloat16(v.y);
    __nv_bfloat16 lx = __float2bfloat16(v.x - __bfloat162float(hx));
    __nv_bfloat16 ly = __float2bfloat16(v.y - __bfloat162float(hy));
    __nv_bfloat162 h2; h2.x = hx; h2.y = hy;
    __nv_bfloat162 l2; l2.x = lx; l2.y = ly;
    __nv_bfloat16* row = g_ws + (size_t)warp * KSP;
    reinterpret_cast<__nv_bfloat162*>(row)[lane]       = h2;
    reinterpret_cast<__nv_bfloat162*>(row + 64)[lane]  = h2;
    reinterpret_cast<__nv_bfloat162*>(row + 128)[lane] = l2;
}

// ---------------- kernel 3: HMMA argmax-dot filter --------------------------
// (round-15 structure, unchanged: 512x512, 3-buffer ring, FMNMX epilogue)
__device__ __forceinline__ void load_b_tile(uint32_t sdst, int kt, int tid) {
    const char* src = (const char*)g_ws + (size_t)kt * 128 * (KSP * 2);
    #pragma unroll
    for (int i = 0; i < 6; ++i) {
        int idx = i * 512 + tid;                 // 3072 16B chunks
        int row = idx / 24, c = idx % 24;
        CP_ASYNC16(sdst + row * PITCH + c * 16, src + row * (KSP * 2) + c * 16);
    }
}

__global__ __launch_bounds__(512, 1) void k_mma() {
    extern __shared__ char smraw[];
    const uint32_t s0 = smem_u32(smraw);
    const uint32_t buf0 = s0, buf1 = s0 + TILE_SM, buf2 = s0 + 2 * TILE_SM;
    float* mBst = reinterpret_cast<float*>(smraw + 3 * TILE_SM);
    int*   mIdx = reinterpret_cast<int*>(smraw + 3 * TILE_SM + 1024);
    float* mSec = reinterpret_cast<float*>(smraw + 3 * TILE_SM + 2048);

    const int tid = threadIdx.x, wid = tid >> 5, lane = tid & 31;
    const int rtile = wid & 7, h = wid >> 3;
    const int q0 = blockIdx.x * 128;

    {
        const char* srcA = (const char*)g_zs + (size_t)q0 * (KSP * 2);
        #pragma unroll
        for (int i = 0; i < 6; ++i) {
            int idx = i * 512 + tid;
            int row = idx / 24, c = idx % 24;
            CP_ASYNC16(buf2 + row * PITCH + c * 16, srcA + row * (KSP * 2) + c * 16);
        }
        CP_COMMIT();
        load_b_tile(buf0, 0, tid); CP_COMMIT();
        load_b_tile(buf1, 1, tid); CP_COMMIT();
    }
    CP_WAIT(2);
    __syncthreads();

    uint32_t af[12][4];
    {
        const uint32_t aaddr = buf2 + (rtile * 16 + (lane & 15)) * PITCH + ((lane >> 4) << 4);
        #pragma unroll
        for (int s = 0; s < 12; ++s)
            LDSM4(af[s][0], af[s][1], af[s][2], af[s][3], aaddr + s * 32);
    }

    const uint32_t boff = (uint32_t)((h * 64 + ((lane >> 4) << 3) + (lane & 7)) * PITCH
                                     + (((lane >> 3) & 1) << 4));

    float v0b = -CUDART_INF_F, v0s = -CUDART_INF_F;
    float v1b = -CUDART_INF_F, v1s = -CUDART_INF_F;
    int   i0 = 0, i1 = 0;

    for (int kt = 0; kt < 64; ++kt) {
        if (kt == 63) { CP_WAIT(0); } else { CP_WAIT(1); }
        __syncthreads();
        if (kt + 2 < 64) {
            uint32_t nb = ((kt + 2) % 3 == 0) ? buf0 : ((kt + 2) % 3 == 1) ? buf1 : buf2;
            load_b_tile(nb, kt + 2, tid);
            CP_COMMIT();
        }
        const uint32_t cur = (kt % 3 == 0) ? buf0 : (kt % 3 == 1) ? buf1 : buf2;

        float acc[32];
        #pragma unroll
        for (int i = 0; i < 32; ++i) acc[i] = 0.0f;

        #pragma unroll
        for (int s = 0; s < 12; ++s) {
            #pragma unroll
            for (int p = 0; p < 4; ++p) {
                uint32_t b0, b1, b2, b3;
                LDSM4(b0, b1, b2, b3, cur + boff + p * 16 * PITCH + s * 32);
                float* d0 = acc + (2 * p) * 4;
                float* d1 = acc + (2 * p + 1) * 4;
                MMA16816(d0[0], d0[1], d0[2], d0[3], af[s][0], af[s][1], af[s][2], af[s][3], b0, b1);
                MMA16816(d1[0], d1[1], d1[2], d1[3], af[s][0], af[s][1], af[s][2], af[s][3], b2, b3);
            }
        }

        int colb = kt * 128 + h * 64 + 2 * (lane & 3);
        #pragma unroll
        for (int t = 0; t < 8; ++t) {
            int cb = colb + t * 8;
            {
                float e0 = acc[t * 4 + 0], e1 = acc[t * 4 + 1];
                float m  = fmaxf(e0, e1);
                float o  = fminf(e0, e1);
                int   ci = (e1 > e0) ? cb + 1 : cb;
                bool up = (m > v0b);
                v0s = up ? fmaxf(v0b, o) : fmaxf(v0s, m);
                i0  = up ? ci : i0;
                v0b = fmaxf(v0b, m);
            }
            {
                float e2 = acc[t * 4 + 2], e3 = acc[t * 4 + 3];
                float m  = fmaxf(e2, e3);
                float o  = fminf(e2, e3);
                int   ci = (e3 > e2) ? cb + 1 : cb;
                bool up = (m > v1b);
                v1s = up ? fmaxf(v1b, o) : fmaxf(v1s, m);
                i1  = up ? ci : i1;
                v1b = fmaxf(v1b, m);
            }
        }
        __syncthreads();
    }

    #pragma unroll
    for (int off = 1; off <= 2; off <<= 1) {
        float ov = __shfl_xor_sync(0xffffffffu, v0b, off);
        int   oi = __shfl_xor_sync(0xffffffffu, i0, off);
        float os = __shfl_xor_sync(0xffffffffu, v0s, off);
        if (ov > v0b || (ov == v0b && oi < i0)) { v0s = fmaxf(v0b, os); v0b = ov; i0 = oi; }
        else v0s = fmaxf(v0s, ov);
        ov = __shfl_xor_sync(0xffffffffu, v1b, off);
        oi = __shfl_xor_sync(0xffffffffu, i1, off);
        os = __shfl_xor_sync(0xffffffffu, v1s, off);
        if (ov > v1b || (ov == v1b && oi < i1)) { v1s = fmaxf(v1b, os); v1b = ov; i1 = oi; }
        else v1s = fmaxf(v1s, ov);
    }
    if ((lane & 3) == 0) {
        int row0 = rtile * 16 + (lane >> 2);
        mBst[h * 128 + row0] = v0b; mIdx[h * 128 + row0] = i0; mSec[h * 128 + row0] = v0s;
        mBst[h * 128 + row0 + 8] = v1b; mIdx[h * 128 + row0 + 8] = i1; mSec[h * 128 + row0 + 8] = v1s;
    }
    __syncthreads();

    if (tid < 128) {
        float vA = mBst[tid], vB = mBst[128 + tid];
        int   iA = mIdx[tid], iB = mIdx[128 + tid];
        float sA2 = mSec[tid], sB2 = mSec[128 + tid];
        float bv; int bidx; float sv;
        if (vB > vA || (vB == vA && iB < iA)) { bv = vB; bidx = iB; sv = vA; }
        else                                  { bv = vA; bidx = iA; sv = vB; }
        sv = fmaxf(sv, fmaxf(sA2, sB2));
        g_enc[q0 + tid] = bidx;
        if (bv - sv < MARGIN) {
            int s = atomicAdd(&g_nflag, 1);
            g_flaglist[s] = q0 + tid;
            g_rkey[s] = 0xFFFFFFFFFFFFFFFFull;
        }
    }
}

// ---------------- kernel 4: exact fp32 rescore (warp-coalesced, chunked) ----
// work unit = (flagged query, 1024-code chunk); one warp scans one code row
// per step with perfectly coalesced 256B loads + shuffle reduce. Result merged
// via atomicMin on a packed (ordered-score | index) key.
__global__ void k_rescore(const float* __restrict__ W) {
    int nf = g_nflag;
    int lane = threadIdx.x & 31;
    int w = threadIdx.x >> 5;                        // 8 warps/block
    for (int b = blockIdx.x; b < nf * 8; b += gridDim.x) {
        int it = b >> 3, chunk = b & 7;
        int q = g_flaglist[it];
        float2 zv = reinterpret_cast<const float2*>(g_zn + (size_t)q * 64)[lane];
        unsigned long long bestkey = 0xFFFFFFFFFFFFFFFFull;
        int k0 = chunk * 1024 + w;
        #pragma unroll 4
        for (int i = 0; i < 128; ++i) {
            int k = k0 + i * 8;
            float2 wv = reinterpret_cast<const float2*>(W + (size_t)k * 64)[lane];
            float d = zv.x * wv.x + zv.y * wv.y;
            #pragma unroll
            for (int off = 16; off > 0; off >>= 1) d += __shfl_xor_sync(0xffffffffu, d, off);
            float s = fmaf(-2.0f, d, g_w2[k]);
            unsigned u = __float_as_uint(s);
            u = (u & 0x80000000u) ? ~u : (u | 0x80000000u);   // ordered-uint
            unsigned long long key = ((unsigned long long)u << 32) | (unsigned)k;
            bestkey = min(bestkey, key);
        }
        if (lane == 0) atomicMin(&g_rkey[it], bestkey);
    }
}

// writeback: enc[flagged] = index part of the winning key
__global__ void k_rescore_fin() {
    int s = blockIdx.x * blockDim.x + threadIdx.x;
    if (s < g_nflag)
        g_enc[g_flaglist[s]] = (int)(g_rkey[s] & 0xFFFFFFFFull);
}

// ---------------- kernel 5: scatter / z_q / loss ----------------------------
__global__ void k_scatter(const float* __restrict__ W, float* __restrict__ out) {
    __shared__ double lsum[8];
    int warp = (blockIdx.x * blockDim.x + threadIdx.x) >> 5;
    int lwid = (threadIdx.x >> 5);
    int lane = threadIdx.x & 31;
    double part_d = 0.0;
    if (warp < NQ) {
        int e = g_enc[warp];
        float2 wv = reinterpret_cast<const float2*>(W)[(size_t)e * 32 + lane];
        float2 zv = reinterpret_cast<const float2*>(g_zn)[(size_t)warp * 32 + lane];
        float d0 = wv.x - zv.x, d1 = wv.y - zv.y;
        reinterpret_cast<float2*>(out + ZQ_OFF)[(size_t)warp * 32 + lane] =
            make_float2(zv.x + d0, zv.y + d1);
        atomicAdd(&g_es[(size_t)e * 64 + 2 * lane],     zv.x);
        atomicAdd(&g_es[(size_t)e * 64 + 2 * lane + 1], zv.y);
        float part = d0 * d0 + d1 * d1;
        #pragma unroll
        for (int off = 16; off > 0; off >>= 1) part += __shfl_xor_sync(0xffffffffu, part, off);
        if (lane == 0) {
            atomicAdd(&g_bins[e], 1.0f);
            out[ENC_OFF + warp] = (float)e;
            part_d = (double)part;
        }
    }
    if (lane == 0) lsum[lwid] = part_d;
    __syncthreads();
    if (threadIdx.x == 0) {
        double s = 0.0;
        #pragma unroll
        for (int i = 0; i < 8; ++i) s += lsum[i];
        atomicAdd(&g_loss, s);
    }
}

// ---------------- kernel 6: per-code EMA updates ----------------------------
__global__ void k_update(const float* __restrict__ W,
                         const float* __restrict__ CS,
                         const float* __restrict__ EA,
                         float* __restrict__ out) {
    int warp = (blockIdx.x * blockDim.x + threadIdx.x) >> 5;
    int lane = threadIdx.x & 31;
    if (blockIdx.x == 0 && threadIdx.x == 0)
        out[LOSS_OFF] = (float)(0.25 * (g_loss / (double)((size_t)NQ * DIM)));
    if (warp >= NK) return;
    int k = warp;
    float b = g_bins[k];
    float2 es = reinterpret_cast<const float2*>(g_es)[(size_t)k * 32 + lane];
    float2 ea = reinterpret_cast<const float2*>(EA)[(size_t)k * 32 + lane];
    out[EA_OFF + (size_t)k * 64 + 2 * lane]     = ea.x * 0.99f + 0.01f * es.x;
    out[EA_OFF + (size_t)k * 64 + 2 * lane + 1] = ea.y * 0.99f + 0.01f * es.y;
    float bc = (b == 0.0f) ? 1.0f : b;
    float vx = es.x / bc, vy = es.y / bc;
    float ss = vx * vx + vy * vy;
    #pragma unroll
    for (int off = 16; off > 0; off >>= 1) ss += __shfl_xor_sync(0xffffffffu, ss, off);
    float inv = 1.0f / fmaxf(sqrtf(ss), 1e-12f);
    float2 wv = reinterpret_cast<const float2*>(W)[(size_t)k * 32 + lane];
    float enx = (b == 0.0f) ? wv.x : vx * inv;
    float eny = (b == 0.0f) ? wv.y : vy * inv;
    float nwx = wv.x * 0.99f + 0.01f * enx;
    float nwy = wv.y * 0.99f + 0.01f * eny;
    float ss2 = nwx * nwx + nwy * nwy;
    #pragma unroll
    for (int off = 16; off > 0; off >>= 1) ss2 += __shfl_xor_sync(0xffffffffu, ss2, off);
    float inv2 = 1.0f / fmaxf(sqrtf(ss2), 1e-12f);
    out[W_OFF + (size_t)k * 64 + 2 * lane]     = nwx * inv2;
    out[W_OFF + (size_t)k * 64 + 2 * lane + 1] = nwy * inv2;
    if (lane == 0) out[CS_OFF + k] = CS[k] * 0.99f + 0.01f * b;
}

// ---------------- launch -----------------------------------------------------
extern "C" void kernel_launch(void* const* d_in, const int* in_sizes, int n_in,
                              void* d_out, int out_size) {
    const float* z  = (const float*)d_in[0];
    const float* w  = (const float*)d_in[1];
    const float* cs = (const float*)d_in[2];
    const float* ea = (const float*)d_in[3];
    float* out = (float*)d_out;

    const int smem_mma = 3 * TILE_SM + 3072;   // 156,672 B (1 block/SM)
    cudaFuncSetAttribute(k_mma, cudaFuncAttributeMaxDynamicSharedMemorySize, smem_mma);

    k_prep_z<<<NQ / 8, 256>>>(z);
    k_prep_w<<<NK / 8, 256>>>(w);
    k_mma<<<NQ / 128, 512, smem_mma>>>();
    k_rescore<<<4096, 256>>>(w);
    k_rescore_fin<<<NQ / 256, 256>>>();
    k_scatter<<<NQ / 8, 256>>>(w, out);
    k_update<<<NK / 8, 256>>>(w, cs, ea, out);
}